// round 1
// baseline (speedup 1.0000x reference)
#include <cuda_runtime.h>
#include <cstdint>

// Problem dims
#define TT 2048
#define BB 16
#define DM 1024
#define DB 128
#define DH 512
#define RWS (TT*BB)           // 32768 rows
#define OUT_MAIN ((size_t)RWS*DM)  // offset of final_mem in d_out

// Scratch (device globals; no runtime allocation allowed)
__device__ float g_H   [RWS*DB];
__device__ float g_Wpre[RWS*DB];
__device__ float g_M   [RWS*DB];
__device__ float g_R   [RWS*DB];
__device__ float g_G   [RWS*DB];
__device__ float g_U1  [RWS*DH];
__device__ float g_U   [RWS*DB];
__device__ float g_G2  [RWS*DB];
__device__ float g_UP  [RWS*DM];

// ---------------------------------------------------------------------------
// Tiled SGEMM: C[M,N] = act(A[M,K] @ B[K,N] + bias[N])
// BM=128, BN=128, BK=16, 256 threads, 8x8 register tile per thread.
// ACT: 0 none, 1 tanh, 2 relu
// ---------------------------------------------------------------------------
template<int ACT>
__global__ void __launch_bounds__(256)
sgemm_bias(const float* __restrict__ A, const float* __restrict__ B,
           const float* __restrict__ bias, float* __restrict__ C,
           int M, int N, int K)
{
    __shared__ float As[16][128];   // transposed: As[k][m]
    __shared__ float Bs[16][128];

    const int tid = threadIdx.x;
    const int bm  = blockIdx.y;
    const int bn  = blockIdx.x;
    const int tx  = tid & 15;       // col group (8 cols each)
    const int ty  = tid >> 4;       // row group (8 rows each)

    const int aRow = tid >> 2;          // 0..63
    const int aCol = (tid & 3) * 4;     // 0,4,8,12
    const int bRow = tid >> 5;          // 0..7
    const int bCol = (tid & 31) * 4;

    const float* Aptr = A + (size_t)bm * 128 * K;
    const float* Bptr = B + (size_t)bn * 128;

    float acc[8][8];
#pragma unroll
    for (int i = 0; i < 8; i++)
#pragma unroll
        for (int j = 0; j < 8; j++) acc[i][j] = 0.f;

    for (int k0 = 0; k0 < K; k0 += 16) {
#pragma unroll
        for (int r = 0; r < 2; r++) {
            int row = aRow + r * 64;
            float4 v = *(const float4*)(Aptr + (size_t)row * K + k0 + aCol);
            As[aCol + 0][row] = v.x;
            As[aCol + 1][row] = v.y;
            As[aCol + 2][row] = v.z;
            As[aCol + 3][row] = v.w;
        }
#pragma unroll
        for (int r = 0; r < 2; r++) {
            int row = bRow + r * 8;
            float4 v = *(const float4*)(Bptr + (size_t)(k0 + row) * N + bCol);
            *(float4*)&Bs[row][bCol] = v;
        }
        __syncthreads();

#pragma unroll
        for (int kk = 0; kk < 16; kk++) {
            float4 ra0 = *(const float4*)&As[kk][ty * 8];
            float4 ra1 = *(const float4*)&As[kk][ty * 8 + 4];
            float4 rb0 = *(const float4*)&Bs[kk][tx * 8];
            float4 rb1 = *(const float4*)&Bs[kk][tx * 8 + 4];
            float ra[8] = {ra0.x, ra0.y, ra0.z, ra0.w, ra1.x, ra1.y, ra1.z, ra1.w};
            float rb[8] = {rb0.x, rb0.y, rb0.z, rb0.w, rb1.x, rb1.y, rb1.z, rb1.w};
#pragma unroll
            for (int i = 0; i < 8; i++)
#pragma unroll
                for (int j = 0; j < 8; j++)
                    acc[i][j] += ra[i] * rb[j];
        }
        __syncthreads();
    }

    // Epilogue
    const int colBase = bn * 128 + tx * 8;
    float bia[8];
#pragma unroll
    for (int j = 0; j < 8; j++) bia[j] = bias[colBase + j];

#pragma unroll
    for (int i = 0; i < 8; i++) {
        int row = bm * 128 + ty * 8 + i;
        float out[8];
#pragma unroll
        for (int j = 0; j < 8; j++) {
            float v = acc[i][j] + bia[j];
            if (ACT == 1) v = tanhf(v);
            else if (ACT == 2) v = fmaxf(v, 0.f);
            out[j] = v;
        }
        float* cp = C + (size_t)row * N + colBase;
        *(float4*)(cp + 0) = make_float4(out[0], out[1], out[2], out[3]);
        *(float4*)(cp + 4) = make_float4(out[4], out[5], out[6], out[7]);
    }
}

// ---------------------------------------------------------------------------
// Elementwise diagonal scan over time: mem[t+1] = mask ? mem : d*mem + (1-d)*w
// One thread per (b,j); stores M[t] (mem entering step t) and final mem.
// ---------------------------------------------------------------------------
__global__ void scan_kernel(const float* __restrict__ Wpre,
                            const unsigned char* __restrict__ mask,
                            const float* __restrict__ mem0,
                            const float* __restrict__ dlogit,
                            float* __restrict__ Mbuf,
                            float* __restrict__ outFinal)
{
    int idx = blockIdx.x * blockDim.x + threadIdx.x;   // 0..2047
    if (idx >= BB * DB) return;
    int bb = idx >> 7;        // batch
    int j  = idx & 127;       // channel
    float d  = 1.f / (1.f + expf(-dlogit[j]));
    float om = 1.f - d;
    float mem = mem0[idx];
#pragma unroll 4
    for (int t = 0; t < TT; t++) {
        Mbuf[(size_t)t * (BB * DB) + idx] = mem;
        float w = Wpre[(size_t)t * (BB * DB) + idx];
        bool mk = mask[t * BB + bb] != 0;
        float nm = d * mem + om * w;
        mem = mk ? mem : nm;
    }
    outFinal[idx] = mem;
}

// ---------------------------------------------------------------------------
// LN over D=128 of (A+B): one warp per row.
// ---------------------------------------------------------------------------
__global__ void ln_add128(const float* __restrict__ A, const float* __restrict__ Bv,
                          const float* __restrict__ s, const float* __restrict__ b,
                          float* __restrict__ O, int rows)
{
    int warp = (blockIdx.x * blockDim.x + threadIdx.x) >> 5;
    int lane = threadIdx.x & 31;
    if (warp >= rows) return;
    const float* a = A  + (size_t)warp * DB;
    const float* c = Bv + (size_t)warp * DB;
    float v[4];
    float sum = 0.f;
#pragma unroll
    for (int i = 0; i < 4; i++) {
        v[i] = a[lane + 32 * i] + c[lane + 32 * i];
        sum += v[i];
    }
#pragma unroll
    for (int off = 16; off >= 1; off >>= 1) sum += __shfl_xor_sync(0xffffffffu, sum, off);
    float mean = sum * (1.f / DB);
    float vs = 0.f;
#pragma unroll
    for (int i = 0; i < 4; i++) {
        float dd = v[i] - mean;
        vs += dd * dd;
    }
#pragma unroll
    for (int off = 16; off >= 1; off >>= 1) vs += __shfl_xor_sync(0xffffffffu, vs, off);
    float inv = rsqrtf(vs * (1.f / DB) + 1e-5f);
    float* o = O + (size_t)warp * DB;
#pragma unroll
    for (int i = 0; i < 4; i++) {
        int e = lane + 32 * i;
        o[e] = (v[i] - mean) * inv * s[e] + b[e];
    }
}

// ---------------------------------------------------------------------------
// Final: out = LN(X + UP) over D_MODEL=1024. One block (256 thr) per row.
// ---------------------------------------------------------------------------
__device__ __forceinline__ float blockReduceSum(float v, float* red)
{
    int lane = threadIdx.x & 31, wid = threadIdx.x >> 5;
#pragma unroll
    for (int off = 16; off >= 1; off >>= 1) v += __shfl_xor_sync(0xffffffffu, v, off);
    if (lane == 0) red[wid] = v;
    __syncthreads();
    float t = (threadIdx.x < 8) ? red[threadIdx.x] : 0.f;
    if (wid == 0) {
#pragma unroll
        for (int off = 4; off >= 1; off >>= 1) t += __shfl_xor_sync(0xffffffffu, t, off);
        if (lane == 0) red[0] = t;
    }
    __syncthreads();
    float r = red[0];
    __syncthreads();
    return r;
}

__global__ void __launch_bounds__(256)
ln_out_kernel(const float* __restrict__ X, const float* __restrict__ UP,
              const float* __restrict__ s, const float* __restrict__ b,
              float* __restrict__ O)
{
    __shared__ float red[8];
    int row = blockIdx.x;
    int tid = threadIdx.x;
    const float4 xv = *(const float4*)(X  + (size_t)row * DM + tid * 4);
    const float4 uv = *(const float4*)(UP + (size_t)row * DM + tid * 4);
    float v[4] = {xv.x + uv.x, xv.y + uv.y, xv.z + uv.z, xv.w + uv.w};
    float sum = v[0] + v[1] + v[2] + v[3];
    sum = blockReduceSum(sum, red);
    float mean = sum * (1.f / DM);
    float vs = 0.f;
#pragma unroll
    for (int i = 0; i < 4; i++) {
        float dd = v[i] - mean;
        vs += dd * dd;
    }
    vs = blockReduceSum(vs, red);
    float inv = rsqrtf(vs * (1.f / DM) + 1e-5f);
    const float4 sv = *(const float4*)(s + tid * 4);
    const float4 bv = *(const float4*)(b + tid * 4);
    float4 ov;
    ov.x = (v[0] - mean) * inv * sv.x + bv.x;
    ov.y = (v[1] - mean) * inv * sv.y + bv.y;
    ov.z = (v[2] - mean) * inv * sv.z + bv.z;
    ov.w = (v[3] - mean) * inv * sv.w + bv.w;
    *(float4*)(O + (size_t)row * DM + tid * 4) = ov;
}

// ---------------------------------------------------------------------------
extern "C" void kernel_launch(void* const* d_in, const int* in_sizes, int n_in,
                              void* d_out, int out_size)
{
    // Input order (setup_inputs dict order):
    const float*         x      = (const float*)d_in[0];
    const unsigned char* mask   = (const unsigned char*)d_in[1];
    const float*         mem0   = (const float*)d_in[2];
    const float*         Wb     = (const float*)d_in[3];
    const float*         bb     = (const float*)d_in[4];
    const float*         Wu     = (const float*)d_in[5];
    const float*         bu     = (const float*)d_in[6];
    const float*         Wr     = (const float*)d_in[7];
    const float*         br     = (const float*)d_in[8];
    const float*         Ww     = (const float*)d_in[9];
    const float*         bw     = (const float*)d_in[10];
    const float*         dlog   = (const float*)d_in[11];
    const float*         ff_w1  = (const float*)d_in[12];
    const float*         ff_b1  = (const float*)d_in[13];
    const float*         ff_w2  = (const float*)d_in[14];
    const float*         ff_b2  = (const float*)d_in[15];
    const float*         mln_s  = (const float*)d_in[16];
    const float*         mln_b  = (const float*)d_in[17];
    const float*         fln_s  = (const float*)d_in[18];
    const float*         fln_b  = (const float*)d_in[19];
    const float*         oln_s  = (const float*)d_in[20];
    const float*         oln_b  = (const float*)d_in[21];

    float* out = (float*)d_out;

    float *H, *Wpre, *M, *R, *G, *U1, *U, *G2, *UP;
    cudaGetSymbolAddress((void**)&H,    g_H);
    cudaGetSymbolAddress((void**)&Wpre, g_Wpre);
    cudaGetSymbolAddress((void**)&M,    g_M);
    cudaGetSymbolAddress((void**)&R,    g_R);
    cudaGetSymbolAddress((void**)&G,    g_G);
    cudaGetSymbolAddress((void**)&U1,   g_U1);
    cudaGetSymbolAddress((void**)&U,    g_U);
    cudaGetSymbolAddress((void**)&G2,   g_G2);
    cudaGetSymbolAddress((void**)&UP,   g_UP);

    const int MR = RWS;  // 32768 rows

    // 1) H = X @ Wb + bb                       [32768,1024]x[1024,128]
    sgemm_bias<0><<<dim3(1, MR / 128), 256>>>(x, Wb, bb, H, MR, DB, DM);
    // 2) Wpre = tanh(H @ Ww + bw)              [32768,128]x[128,128]
    sgemm_bias<1><<<dim3(1, MR / 128), 256>>>(H, Ww, bw, Wpre, MR, DB, DB);
    // 3) diagonal scan -> M[t], final mem
    scan_kernel<<<2, 1024>>>(Wpre, mask, mem0, dlog, M, out + OUT_MAIN);
    // 4) R = M @ Wr + br
    sgemm_bias<0><<<dim3(1, MR / 128), 256>>>(M, Wr, br, R, MR, DB, DB);
    // 5) G = LN(H + R)
    ln_add128<<<MR / 8, 256>>>(H, R, mln_s, mln_b, G, MR);
    // 6) U1 = relu(G @ ff_w1 + ff_b1)          [32768,128]x[128,512]
    sgemm_bias<2><<<dim3(DH / 128, MR / 128), 256>>>(G, ff_w1, ff_b1, U1, MR, DH, DB);
    // 7) U = U1 @ ff_w2 + ff_b2                [32768,512]x[512,128]
    sgemm_bias<0><<<dim3(1, MR / 128), 256>>>(U1, ff_w2, ff_b2, U, MR, DB, DH);
    // 8) G2 = LN(G + U)
    ln_add128<<<MR / 8, 256>>>(G, U, fln_s, fln_b, G2, MR);
    // 9) UP = G2 @ Wu + bu                     [32768,128]x[128,1024]
    sgemm_bias<0><<<dim3(DM / 128, MR / 128), 256>>>(G2, Wu, bu, UP, MR, DM, DB);
    // 10) out = LN(X + UP)
    ln_out_kernel<<<MR, 256>>>(x, UP, oln_s, oln_b, out);
}

// round 2
// speedup vs baseline: 1.9450x; 1.9450x over previous
#include <cuda_runtime.h>
#include <cstdint>

// Problem dims
#define TT 2048
#define BB 16
#define DM 1024
#define DB 128
#define DH 512
#define RWS (TT*BB)                 // 32768 rows
#define OUT_MAIN ((size_t)RWS*DM)   // offset of final_mem in d_out

#define NCH 64                      // scan chunks
#define CHLEN (TT/NCH)              // 32

// Scratch (device globals; no runtime allocation allowed)
__device__ float g_H   [RWS*DB];
__device__ float g_Wpre[RWS*DB];
__device__ float g_M   [RWS*DB];
__device__ float g_R   [RWS*DB];
__device__ float g_G   [RWS*DB];
__device__ float g_U1  [RWS*DH];
__device__ float g_U   [RWS*DB];
__device__ float g_G2  [RWS*DB];
__device__ float g_UP  [RWS*DM];
__device__ float g_Aseg [NCH*BB*DB];
__device__ float g_Cseg [NCH*BB*DB];
__device__ float g_Carry[NCH*BB*DB];

// ---------------------------------------------------------------------------
// TF32 tensor-core GEMM: C[M,N] = act(A[M,K] @ B[K,N] + bias[N])
// BM=128, BN=64, BK=16, 256 threads (8 warps, 4m x 2n), warp tile 32x32.
// mma.sync.aligned.m16n8k8 tf32, fp32 accumulate. Double-buffered smem.
// ACT: 0 none, 1 tanh, 2 relu
// ---------------------------------------------------------------------------
__device__ __forceinline__ float to_tf32(float x) {
    uint32_t u;
    asm("cvt.rna.tf32.f32 %0, %1;" : "=r"(u) : "f"(x));
    return __uint_as_float(u);
}

__device__ __forceinline__ void mma_tf32(float* d, const float* a, const float* b) {
    asm volatile(
        "mma.sync.aligned.m16n8k8.row.col.f32.tf32.tf32.f32 "
        "{%0,%1,%2,%3}, {%4,%5,%6,%7}, {%8,%9}, {%0,%1,%2,%3};"
        : "+f"(d[0]), "+f"(d[1]), "+f"(d[2]), "+f"(d[3])
        : "r"(__float_as_uint(a[0])), "r"(__float_as_uint(a[1])),
          "r"(__float_as_uint(a[2])), "r"(__float_as_uint(a[3])),
          "r"(__float_as_uint(b[0])), "r"(__float_as_uint(b[1])));
}

#define ASTRIDE 136   // 128 + 8 pad: conflict-free frag loads (8k+m distinct)
#define BSTRIDE 72    // 64 + 8 pad

template<int ACT>
__global__ void __launch_bounds__(256)
gemm_tf32(const float* __restrict__ A, const float* __restrict__ B,
          const float* __restrict__ bias, float* __restrict__ C,
          int M, int N, int K)
{
    __shared__ float As[2][16 * ASTRIDE];
    __shared__ float Bs[2][16 * BSTRIDE];

    const int tid  = threadIdx.x;
    const int warp = tid >> 5, lane = tid & 31;
    const int gid  = lane >> 2, tig = lane & 3;
    const int wm   = warp >> 1, wn = warp & 1;
    const int bm   = blockIdx.y, bn = blockIdx.x;

    const float* Ablk = A + (size_t)bm * 128 * K;
    const float* Bblk = B + bn * 64;

    // loader indices
    const int aRow = tid >> 2;          // 0..63 (+64 for second row)
    const int aCol = (tid & 3) << 2;    // 0,4,8,12
    const int bRow = tid >> 4;          // 0..15
    const int bCol = (tid & 15) << 2;   // 0..60

    float acc[2][4][4];
#pragma unroll
    for (int mt = 0; mt < 2; mt++)
#pragma unroll
        for (int nt = 0; nt < 4; nt++)
#pragma unroll
            for (int i = 0; i < 4; i++) acc[mt][nt][i] = 0.f;

    // preload tile 0
    {
        float4 va0 = *(const float4*)(Ablk + (size_t)aRow * K + aCol);
        float4 va1 = *(const float4*)(Ablk + (size_t)(aRow + 64) * K + aCol);
        float4 vb  = *(const float4*)(Bblk + (size_t)bRow * N + bCol);
        float* as_ = As[0];
        as_[(aCol + 0) * ASTRIDE + aRow] = to_tf32(va0.x);
        as_[(aCol + 1) * ASTRIDE + aRow] = to_tf32(va0.y);
        as_[(aCol + 2) * ASTRIDE + aRow] = to_tf32(va0.z);
        as_[(aCol + 3) * ASTRIDE + aRow] = to_tf32(va0.w);
        as_[(aCol + 0) * ASTRIDE + aRow + 64] = to_tf32(va1.x);
        as_[(aCol + 1) * ASTRIDE + aRow + 64] = to_tf32(va1.y);
        as_[(aCol + 2) * ASTRIDE + aRow + 64] = to_tf32(va1.z);
        as_[(aCol + 3) * ASTRIDE + aRow + 64] = to_tf32(va1.w);
        float* bs_ = Bs[0];
        bs_[bRow * BSTRIDE + bCol + 0] = to_tf32(vb.x);
        bs_[bRow * BSTRIDE + bCol + 1] = to_tf32(vb.y);
        bs_[bRow * BSTRIDE + bCol + 2] = to_tf32(vb.z);
        bs_[bRow * BSTRIDE + bCol + 3] = to_tf32(vb.w);
    }
    __syncthreads();

    int buf = 0;
    for (int k0 = 0; k0 < K; k0 += 16) {
        const bool has_next = (k0 + 16) < K;
        float4 na0, na1, nb;
        if (has_next) {
            na0 = *(const float4*)(Ablk + (size_t)aRow * K + k0 + 16 + aCol);
            na1 = *(const float4*)(Ablk + (size_t)(aRow + 64) * K + k0 + 16 + aCol);
            nb  = *(const float4*)(Bblk + (size_t)(k0 + 16 + bRow) * N + bCol);
        }

        const float* as_ = As[buf];
        const float* bs_ = Bs[buf];
#pragma unroll
        for (int kk = 0; kk < 16; kk += 8) {
            float af[2][4], bf[4][2];
#pragma unroll
            for (int mt = 0; mt < 2; mt++) {
                const int r = wm * 32 + mt * 16 + gid;
                af[mt][0] = as_[(kk + tig) * ASTRIDE + r];
                af[mt][1] = as_[(kk + tig) * ASTRIDE + r + 8];
                af[mt][2] = as_[(kk + tig + 4) * ASTRIDE + r];
                af[mt][3] = as_[(kk + tig + 4) * ASTRIDE + r + 8];
            }
#pragma unroll
            for (int nt = 0; nt < 4; nt++) {
                const int c = wn * 32 + nt * 8 + gid;
                bf[nt][0] = bs_[(kk + tig) * BSTRIDE + c];
                bf[nt][1] = bs_[(kk + tig + 4) * BSTRIDE + c];
            }
#pragma unroll
            for (int mt = 0; mt < 2; mt++)
#pragma unroll
                for (int nt = 0; nt < 4; nt++)
                    mma_tf32(acc[mt][nt], af[mt], bf[nt]);
        }

        if (has_next) {
            float* asn = As[buf ^ 1];
            asn[(aCol + 0) * ASTRIDE + aRow] = to_tf32(na0.x);
            asn[(aCol + 1) * ASTRIDE + aRow] = to_tf32(na0.y);
            asn[(aCol + 2) * ASTRIDE + aRow] = to_tf32(na0.z);
            asn[(aCol + 3) * ASTRIDE + aRow] = to_tf32(na0.w);
            asn[(aCol + 0) * ASTRIDE + aRow + 64] = to_tf32(na1.x);
            asn[(aCol + 1) * ASTRIDE + aRow + 64] = to_tf32(na1.y);
            asn[(aCol + 2) * ASTRIDE + aRow + 64] = to_tf32(na1.z);
            asn[(aCol + 3) * ASTRIDE + aRow + 64] = to_tf32(na1.w);
            float* bsn = Bs[buf ^ 1];
            bsn[bRow * BSTRIDE + bCol + 0] = to_tf32(nb.x);
            bsn[bRow * BSTRIDE + bCol + 1] = to_tf32(nb.y);
            bsn[bRow * BSTRIDE + bCol + 2] = to_tf32(nb.z);
            bsn[bRow * BSTRIDE + bCol + 3] = to_tf32(nb.w);
            buf ^= 1;
            __syncthreads();
        }
    }

    // Epilogue
#pragma unroll
    for (int mt = 0; mt < 2; mt++) {
        const int r0 = bm * 128 + wm * 32 + mt * 16 + gid;
#pragma unroll
        for (int nt = 0; nt < 4; nt++) {
            const int c0 = bn * 64 + wn * 32 + nt * 8 + 2 * tig;
            const float bi0 = bias[c0], bi1 = bias[c0 + 1];
            float v0 = acc[mt][nt][0] + bi0;
            float v1 = acc[mt][nt][1] + bi1;
            float v2 = acc[mt][nt][2] + bi0;
            float v3 = acc[mt][nt][3] + bi1;
            if (ACT == 1) { v0 = tanhf(v0); v1 = tanhf(v1); v2 = tanhf(v2); v3 = tanhf(v3); }
            else if (ACT == 2) { v0 = fmaxf(v0, 0.f); v1 = fmaxf(v1, 0.f); v2 = fmaxf(v2, 0.f); v3 = fmaxf(v3, 0.f); }
            *(float2*)(C + (size_t)r0 * N + c0)       = make_float2(v0, v1);
            *(float2*)(C + (size_t)(r0 + 8) * N + c0) = make_float2(v2, v3);
        }
    }
}

// ---------------------------------------------------------------------------
// Parallel chunked scan over time. Recurrence per (b,j):
//   m_{t+1} = a_t * m_t + c_t,  a_t = mask ? 1 : d,  c_t = mask ? 0 : (1-d)*w_t
// Pass1: per-chunk composition (A, C). Pass2: carries across chunks.
// Pass3: emit M[t] (mem entering step t).
// ---------------------------------------------------------------------------
__global__ void scan_pass1(const float* __restrict__ Wpre,
                           const unsigned char* __restrict__ mask,
                           const float* __restrict__ dlogit,
                           float* __restrict__ Aseg, float* __restrict__ Cseg)
{
    const int idx = blockIdx.x * blockDim.x + threadIdx.x;   // 0..2047
    const int ch  = blockIdx.y;
    const int bb  = idx >> 7;
    const int j   = idx & 127;
    const float d  = 1.f / (1.f + expf(-dlogit[j]));
    const float om = 1.f - d;
    float A = 1.f, C = 0.f;
    const int t0 = ch * CHLEN;
#pragma unroll 4
    for (int t = t0; t < t0 + CHLEN; t++) {
        const bool mk = mask[t * BB + bb] != 0;
        const float a = mk ? 1.f : d;
        const float c = mk ? 0.f : om * Wpre[(size_t)t * (BB * DB) + idx];
        A = a * A;
        C = a * C + c;
    }
    Aseg[ch * (BB * DB) + idx] = A;
    Cseg[ch * (BB * DB) + idx] = C;
}

__global__ void scan_pass2(const float* __restrict__ Aseg,
                           const float* __restrict__ Cseg,
                           const float* __restrict__ mem0,
                           float* __restrict__ Carry,
                           float* __restrict__ outFinal)
{
    const int idx = blockIdx.x * blockDim.x + threadIdx.x;
    if (idx >= BB * DB) return;
    float m = mem0[idx];
#pragma unroll 4
    for (int ch = 0; ch < NCH; ch++) {
        Carry[ch * (BB * DB) + idx] = m;
        m = Aseg[ch * (BB * DB) + idx] * m + Cseg[ch * (BB * DB) + idx];
    }
    outFinal[idx] = m;
}

__global__ void scan_pass3(const float* __restrict__ Wpre,
                           const unsigned char* __restrict__ mask,
                           const float* __restrict__ dlogit,
                           const float* __restrict__ Carry,
                           float* __restrict__ Mbuf)
{
    const int idx = blockIdx.x * blockDim.x + threadIdx.x;
    const int ch  = blockIdx.y;
    const int bb  = idx >> 7;
    const int j   = idx & 127;
    const float d  = 1.f / (1.f + expf(-dlogit[j]));
    const float om = 1.f - d;
    float m = Carry[ch * (BB * DB) + idx];
    const int t0 = ch * CHLEN;
#pragma unroll 4
    for (int t = t0; t < t0 + CHLEN; t++) {
        Mbuf[(size_t)t * (BB * DB) + idx] = m;
        const bool mk = mask[t * BB + bb] != 0;
        const float w = Wpre[(size_t)t * (BB * DB) + idx];
        const float nm = d * m + om * w;
        m = mk ? m : nm;
    }
}

// ---------------------------------------------------------------------------
// LN over D=128 of (A+B): one warp per row, float4.
// ---------------------------------------------------------------------------
__global__ void ln_add128(const float* __restrict__ A, const float* __restrict__ Bv,
                          const float* __restrict__ s, const float* __restrict__ b,
                          float* __restrict__ O, int rows)
{
    const int warp = (blockIdx.x * blockDim.x + threadIdx.x) >> 5;
    const int lane = threadIdx.x & 31;
    if (warp >= rows) return;
    const float4 av = *(const float4*)(A  + (size_t)warp * DB + lane * 4);
    const float4 cv = *(const float4*)(Bv + (size_t)warp * DB + lane * 4);
    float v[4] = {av.x + cv.x, av.y + cv.y, av.z + cv.z, av.w + cv.w};
    float sum = v[0] + v[1] + v[2] + v[3];
#pragma unroll
    for (int off = 16; off >= 1; off >>= 1) sum += __shfl_xor_sync(0xffffffffu, sum, off);
    const float mean = sum * (1.f / DB);
    float vs = 0.f;
#pragma unroll
    for (int i = 0; i < 4; i++) { const float dd = v[i] - mean; vs += dd * dd; }
#pragma unroll
    for (int off = 16; off >= 1; off >>= 1) vs += __shfl_xor_sync(0xffffffffu, vs, off);
    const float inv = rsqrtf(vs * (1.f / DB) + 1e-5f);
    const float4 sv = *(const float4*)(s + lane * 4);
    const float4 bv = *(const float4*)(b + lane * 4);
    float4 ov;
    ov.x = (v[0] - mean) * inv * sv.x + bv.x;
    ov.y = (v[1] - mean) * inv * sv.y + bv.y;
    ov.z = (v[2] - mean) * inv * sv.z + bv.z;
    ov.w = (v[3] - mean) * inv * sv.w + bv.w;
    *(float4*)(O + (size_t)warp * DB + lane * 4) = ov;
}

// ---------------------------------------------------------------------------
// Final: out = LN(X + UP) over D_MODEL=1024. One block (256 thr) per row.
// ---------------------------------------------------------------------------
__device__ __forceinline__ float blockReduceSum(float v, float* red)
{
    const int lane = threadIdx.x & 31, wid = threadIdx.x >> 5;
#pragma unroll
    for (int off = 16; off >= 1; off >>= 1) v += __shfl_xor_sync(0xffffffffu, v, off);
    if (lane == 0) red[wid] = v;
    __syncthreads();
    float t = (threadIdx.x < 8) ? red[threadIdx.x] : 0.f;
    if (wid == 0) {
#pragma unroll
        for (int off = 4; off >= 1; off >>= 1) t += __shfl_xor_sync(0xffffffffu, t, off);
        if (lane == 0) red[0] = t;
    }
    __syncthreads();
    const float r = red[0];
    __syncthreads();
    return r;
}

__global__ void __launch_bounds__(256)
ln_out_kernel(const float* __restrict__ X, const float* __restrict__ UP,
              const float* __restrict__ s, const float* __restrict__ b,
              float* __restrict__ O)
{
    __shared__ float red[8];
    const int row = blockIdx.x;
    const int tid = threadIdx.x;
    const float4 xv = *(const float4*)(X  + (size_t)row * DM + tid * 4);
    const float4 uv = *(const float4*)(UP + (size_t)row * DM + tid * 4);
    float v[4] = {xv.x + uv.x, xv.y + uv.y, xv.z + uv.z, xv.w + uv.w};
    float sum = v[0] + v[1] + v[2] + v[3];
    sum = blockReduceSum(sum, red);
    const float mean = sum * (1.f / DM);
    float vs = 0.f;
#pragma unroll
    for (int i = 0; i < 4; i++) { const float dd = v[i] - mean; vs += dd * dd; }
    vs = blockReduceSum(vs, red);
    const float inv = rsqrtf(vs * (1.f / DM) + 1e-5f);
    const float4 sv = *(const float4*)(s + tid * 4);
    const float4 bv = *(const float4*)(b + tid * 4);
    float4 ov;
    ov.x = (v[0] - mean) * inv * sv.x + bv.x;
    ov.y = (v[1] - mean) * inv * sv.y + bv.y;
    ov.z = (v[2] - mean) * inv * sv.z + bv.z;
    ov.w = (v[3] - mean) * inv * sv.w + bv.w;
    *(float4*)(O + (size_t)row * DM + tid * 4) = ov;
}

// ---------------------------------------------------------------------------
extern "C" void kernel_launch(void* const* d_in, const int* in_sizes, int n_in,
                              void* d_out, int out_size)
{
    const float*         x      = (const float*)d_in[0];
    const unsigned char* mask   = (const unsigned char*)d_in[1];
    const float*         mem0   = (const float*)d_in[2];
    const float*         Wb     = (const float*)d_in[3];
    const float*         bb     = (const float*)d_in[4];
    const float*         Wu     = (const float*)d_in[5];
    const float*         bu     = (const float*)d_in[6];
    const float*         Wr     = (const float*)d_in[7];
    const float*         br     = (const float*)d_in[8];
    const float*         Ww     = (const float*)d_in[9];
    const float*         bw     = (const float*)d_in[10];
    const float*         dlog   = (const float*)d_in[11];
    const float*         ff_w1  = (const float*)d_in[12];
    const float*         ff_b1  = (const float*)d_in[13];
    const float*         ff_w2  = (const float*)d_in[14];
    const float*         ff_b2  = (const float*)d_in[15];
    const float*         mln_s  = (const float*)d_in[16];
    const float*         mln_b  = (const float*)d_in[17];
    const float*         fln_s  = (const float*)d_in[18];
    const float*         fln_b  = (const float*)d_in[19];
    const float*         oln_s  = (const float*)d_in[20];
    const float*         oln_b  = (const float*)d_in[21];

    float* out = (float*)d_out;

    float *H, *Wpre, *M, *R, *G, *U1, *U, *G2, *UP, *Aseg, *Cseg, *Carry;
    cudaGetSymbolAddress((void**)&H,     g_H);
    cudaGetSymbolAddress((void**)&Wpre,  g_Wpre);
    cudaGetSymbolAddress((void**)&M,     g_M);
    cudaGetSymbolAddress((void**)&R,     g_R);
    cudaGetSymbolAddress((void**)&G,     g_G);
    cudaGetSymbolAddress((void**)&U1,    g_U1);
    cudaGetSymbolAddress((void**)&U,     g_U);
    cudaGetSymbolAddress((void**)&G2,    g_G2);
    cudaGetSymbolAddress((void**)&UP,    g_UP);
    cudaGetSymbolAddress((void**)&Aseg,  g_Aseg);
    cudaGetSymbolAddress((void**)&Cseg,  g_Cseg);
    cudaGetSymbolAddress((void**)&Carry, g_Carry);

    const int MR = RWS;  // 32768 rows

    // 1) H = X @ Wb + bb                       [32768,1024]x[1024,128]
    gemm_tf32<0><<<dim3(DB / 64, MR / 128), 256>>>(x, Wb, bb, H, MR, DB, DM);
    // 2) Wpre = tanh(H @ Ww + bw)              [32768,128]x[128,128]
    gemm_tf32<1><<<dim3(DB / 64, MR / 128), 256>>>(H, Ww, bw, Wpre, MR, DB, DB);
    // 3) parallel diagonal scan -> M[t], final mem
    scan_pass1<<<dim3(8, NCH), 256>>>(Wpre, mask, dlog, Aseg, Cseg);
    scan_pass2<<<8, 256>>>(Aseg, Cseg, mem0, Carry, out + OUT_MAIN);
    scan_pass3<<<dim3(8, NCH), 256>>>(Wpre, mask, dlog, Carry, M);
    // 4) R = M @ Wr + br
    gemm_tf32<0><<<dim3(DB / 64, MR / 128), 256>>>(M, Wr, br, R, MR, DB, DB);
    // 5) G = LN(H + R)
    ln_add128<<<MR / 8, 256>>>(H, R, mln_s, mln_b, G, MR);
    // 6) U1 = relu(G @ ff_w1 + ff_b1)          [32768,128]x[128,512]
    gemm_tf32<2><<<dim3(DH / 64, MR / 128), 256>>>(G, ff_w1, ff_b1, U1, MR, DH, DB);
    // 7) U = U1 @ ff_w2 + ff_b2                [32768,512]x[512,128]
    gemm_tf32<0><<<dim3(DB / 64, MR / 128), 256>>>(U1, ff_w2, ff_b2, U, MR, DB, DH);
    // 8) G2 = LN(G + U)
    ln_add128<<<MR / 8, 256>>>(G, U, fln_s, fln_b, G2, MR);
    // 9) UP = G2 @ Wu + bu                     [32768,128]x[128,1024]
    gemm_tf32<0><<<dim3(DM / 64, MR / 128), 256>>>(G2, Wu, bu, UP, MR, DM, DB);
    // 10) out = LN(X + UP)
    ln_out_kernel<<<MR, 256>>>(x, UP, oln_s, oln_b, out);
}

// round 3
// speedup vs baseline: 2.1645x; 1.1129x over previous
#include <cuda_runtime.h>
#include <cstdint>

// Problem dims
#define TT 2048
#define BB 16
#define DM 1024
#define DB 128
#define DH 512
#define RWS (TT*BB)                 // 32768 rows
#define OUT_MAIN ((size_t)RWS*DM)   // offset of final_mem in d_out

#define NCH 32                      // scan chunks (warp-scan in pass2)
#define CHLEN (TT/NCH)              // 64
#define LANES (BB*DB)               // 2048 scan lanes

// Scratch (device globals; no runtime allocation allowed)
__device__ float g_H   [RWS*DB];
__device__ float g_Wpre[RWS*DB];
__device__ float g_M   [RWS*DB];
__device__ float g_G   [RWS*DB];
__device__ float g_U1  [RWS*DH];
__device__ float g_G2  [RWS*DB];
__device__ float g_UP  [RWS*DM];
__device__ float g_Aseg [NCH*LANES];
__device__ float g_Cseg [NCH*LANES];
__device__ float g_Carry[NCH*LANES];

// ---------------------------------------------------------------------------
__device__ __forceinline__ float to_tf32(float x) {
    uint32_t u;
    asm("cvt.rna.tf32.f32 %0, %1;" : "=r"(u) : "f"(x));
    return __uint_as_float(u);
}

__device__ __forceinline__ void mma_tf32(float* d, const float* a, const float* b) {
    asm volatile(
        "mma.sync.aligned.m16n8k8.row.col.f32.tf32.tf32.f32 "
        "{%0,%1,%2,%3}, {%4,%5,%6,%7}, {%8,%9}, {%0,%1,%2,%3};"
        : "+f"(d[0]), "+f"(d[1]), "+f"(d[2]), "+f"(d[3])
        : "r"(__float_as_uint(a[0])), "r"(__float_as_uint(a[1])),
          "r"(__float_as_uint(a[2])), "r"(__float_as_uint(a[3])),
          "r"(__float_as_uint(b[0])), "r"(__float_as_uint(b[1])));
}

// ---------------------------------------------------------------------------
// TF32 GEMM: C = act(A[M,K] @ B[K,N] + bias)  (+optional fused residual+LN)
// BM=128, BN=128, BK=16, 256 threads, 8 warps (4m x 2n), warp tile 32x64.
// A smem: k-permuted compact [m][16]: element (m,k) at m*16 + (k&3)*4 + (k>>2)
//   -> one lds.128 per (row, tig) yields k = {tig, tig+4, tig+8, tig+12}.
// B smem: [k][n], stride 136 (conflict-free scalar frag loads).
// ACT: 0 none, 1 tanh, 2 relu.  FUSE_LN: epilogue does LN(acc+bias+resid).
// ---------------------------------------------------------------------------
#define BSTR 136

template<int ACT, int FUSE_LN>
__global__ void __launch_bounds__(256)
gemm_tf32(const float* __restrict__ A, const float* __restrict__ B,
          const float* __restrict__ bias,
          const float* __restrict__ resid,
          const float* __restrict__ ln_s, const float* __restrict__ ln_b,
          float* __restrict__ C, int M, int N, int K)
{
    __shared__ float As[2][128 * 16];
    __shared__ float Bs[2][16 * BSTR];
    __shared__ float2 red[128][2];   // (sum, sumsq) per row per n-half

    const int tid  = threadIdx.x;
    const int warp = tid >> 5, lane = tid & 31;
    const int gid  = lane >> 2, tig = lane & 3;
    const int wm   = warp >> 1, wn = warp & 1;
    const int bm   = blockIdx.y, bn = blockIdx.x;

    const float* Ablk = A + (size_t)bm * 128 * K;
    const float* Bblk = B + bn * 128;

    // loader indices
    const int aRow = tid >> 1;            // 0..127
    const int aQ   = (tid & 1) * 2;       // quad index: 0 or 2 (q and q+1)
    const int bRow = tid >> 4;            // 0..15
    const int bCol = (tid & 15) * 8;      // 0..120

    float acc[2][8][4];
#pragma unroll
    for (int mt = 0; mt < 2; mt++)
#pragma unroll
        for (int nt = 0; nt < 8; nt++)
#pragma unroll
            for (int i = 0; i < 4; i++) acc[mt][nt][i] = 0.f;

    // --- stage tile 0 ---
    {
        float4 va0 = *(const float4*)(Ablk + (size_t)aRow * K + aQ * 4);
        float4 va1 = *(const float4*)(Ablk + (size_t)aRow * K + aQ * 4 + 4);
        float4 vb0 = *(const float4*)(Bblk + (size_t)bRow * N + bCol);
        float4 vb1 = *(const float4*)(Bblk + (size_t)bRow * N + bCol + 4);
        float* as_ = As[0];
        as_[aRow * 16 + 0  + aQ]     = to_tf32(va0.x);
        as_[aRow * 16 + 4  + aQ]     = to_tf32(va0.y);
        as_[aRow * 16 + 8  + aQ]     = to_tf32(va0.z);
        as_[aRow * 16 + 12 + aQ]     = to_tf32(va0.w);
        as_[aRow * 16 + 0  + aQ + 1] = to_tf32(va1.x);
        as_[aRow * 16 + 4  + aQ + 1] = to_tf32(va1.y);
        as_[aRow * 16 + 8  + aQ + 1] = to_tf32(va1.z);
        as_[aRow * 16 + 12 + aQ + 1] = to_tf32(va1.w);
        float* bs_ = Bs[0];
        *(float4*)&bs_[bRow * BSTR + bCol] =
            make_float4(to_tf32(vb0.x), to_tf32(vb0.y), to_tf32(vb0.z), to_tf32(vb0.w));
        *(float4*)&bs_[bRow * BSTR + bCol + 4] =
            make_float4(to_tf32(vb1.x), to_tf32(vb1.y), to_tf32(vb1.z), to_tf32(vb1.w));
    }
    __syncthreads();

    int buf = 0;
    for (int k0 = 0; k0 < K; k0 += 16) {
        const bool has_next = (k0 + 16) < K;
        float4 na0, na1, nb0, nb1;
        if (has_next) {
            na0 = *(const float4*)(Ablk + (size_t)aRow * K + k0 + 16 + aQ * 4);
            na1 = *(const float4*)(Ablk + (size_t)aRow * K + k0 + 16 + aQ * 4 + 4);
            nb0 = *(const float4*)(Bblk + (size_t)(k0 + 16 + bRow) * N + bCol);
            nb1 = *(const float4*)(Bblk + (size_t)(k0 + 16 + bRow) * N + bCol + 4);
        }

        const float* as_ = As[buf];
        const float* bs_ = Bs[buf];

        // A fragments: one lds.128 per (mt, row-half) covers all 16 k
        float4 a0[2], a1[2];
#pragma unroll
        for (int mt = 0; mt < 2; mt++) {
            const int r = wm * 32 + mt * 16 + gid;
            a0[mt] = *(const float4*)&as_[r * 16 + 4 * tig];
            a1[mt] = *(const float4*)&as_[(r + 8) * 16 + 4 * tig];
        }

#pragma unroll
        for (int ph = 0; ph < 2; ph++) {   // kk = 0, 8
            const int kk = ph * 8;
            float bf[8][2];
#pragma unroll
            for (int nt = 0; nt < 8; nt++) {
                const int c = wn * 64 + nt * 8 + gid;
                bf[nt][0] = bs_[(kk + tig) * BSTR + c];
                bf[nt][1] = bs_[(kk + tig + 4) * BSTR + c];
            }
#pragma unroll
            for (int mt = 0; mt < 2; mt++) {
                float af[4];
                if (ph == 0) {
                    af[0] = a0[mt].x; af[1] = a1[mt].x;
                    af[2] = a0[mt].y; af[3] = a1[mt].y;
                } else {
                    af[0] = a0[mt].z; af[1] = a1[mt].z;
                    af[2] = a0[mt].w; af[3] = a1[mt].w;
                }
#pragma unroll
                for (int nt = 0; nt < 8; nt++)
                    mma_tf32(acc[mt][nt], af, bf[nt]);
            }
        }

        if (has_next) {
            float* asn = As[buf ^ 1];
            asn[aRow * 16 + 0  + aQ]     = to_tf32(na0.x);
            asn[aRow * 16 + 4  + aQ]     = to_tf32(na0.y);
            asn[aRow * 16 + 8  + aQ]     = to_tf32(na0.z);
            asn[aRow * 16 + 12 + aQ]     = to_tf32(na0.w);
            asn[aRow * 16 + 0  + aQ + 1] = to_tf32(na1.x);
            asn[aRow * 16 + 4  + aQ + 1] = to_tf32(na1.y);
            asn[aRow * 16 + 8  + aQ + 1] = to_tf32(na1.z);
            asn[aRow * 16 + 12 + aQ + 1] = to_tf32(na1.w);
            float* bsn = Bs[buf ^ 1];
            *(float4*)&bsn[bRow * BSTR + bCol] =
                make_float4(to_tf32(nb0.x), to_tf32(nb0.y), to_tf32(nb0.z), to_tf32(nb0.w));
            *(float4*)&bsn[bRow * BSTR + bCol + 4] =
                make_float4(to_tf32(nb1.x), to_tf32(nb1.y), to_tf32(nb1.z), to_tf32(nb1.w));
            buf ^= 1;
            __syncthreads();
        }
    }

    // ---------------- Epilogue ----------------
    if (FUSE_LN) {
        // bias + residual into acc; then LN over the 128 cols of each row.
        float sum[2][2], sq[2][2];
#pragma unroll
        for (int mt = 0; mt < 2; mt++) { sum[mt][0] = sum[mt][1] = 0.f; sq[mt][0] = sq[mt][1] = 0.f; }

#pragma unroll
        for (int mt = 0; mt < 2; mt++) {
            const int lr0 = wm * 32 + mt * 16 + gid;       // block-local row
            const int gr0 = bm * 128 + lr0;
#pragma unroll
            for (int nt = 0; nt < 8; nt++) {
                const int c0 = wn * 64 + nt * 8 + 2 * tig;
                const float bi0 = bias[c0], bi1 = bias[c0 + 1];
                const float2 rA = *(const float2*)(resid + (size_t)gr0 * 128 + c0);
                const float2 rB = *(const float2*)(resid + (size_t)(gr0 + 8) * 128 + c0);
                acc[mt][nt][0] += bi0 + rA.x;
                acc[mt][nt][1] += bi1 + rA.y;
                acc[mt][nt][2] += bi0 + rB.x;
                acc[mt][nt][3] += bi1 + rB.y;
#pragma unroll
                for (int h = 0; h < 2; h++) {
                    const float v0 = acc[mt][nt][2 * h], v1 = acc[mt][nt][2 * h + 1];
                    sum[mt][h] += v0 + v1;
                    sq[mt][h]  += v0 * v0 + v1 * v1;
                }
            }
        }
        // reduce across tig (4 consecutive lanes)
#pragma unroll
        for (int mt = 0; mt < 2; mt++)
#pragma unroll
            for (int h = 0; h < 2; h++) {
#pragma unroll
                for (int off = 1; off <= 2; off <<= 1) {
                    sum[mt][h] += __shfl_xor_sync(0xffffffffu, sum[mt][h], off);
                    sq[mt][h]  += __shfl_xor_sync(0xffffffffu, sq[mt][h], off);
                }
            }
        if (tig == 0) {
#pragma unroll
            for (int mt = 0; mt < 2; mt++) {
                const int lr0 = wm * 32 + mt * 16 + gid;
                red[lr0][wn]     = make_float2(sum[mt][0], sq[mt][0]);
                red[lr0 + 8][wn] = make_float2(sum[mt][1], sq[mt][1]);
            }
        }
        __syncthreads();

#pragma unroll
        for (int mt = 0; mt < 2; mt++) {
            const int lr0 = wm * 32 + mt * 16 + gid;
            const int gr0 = bm * 128 + lr0;
#pragma unroll
            for (int h = 0; h < 2; h++) {
                const int lr = lr0 + 8 * h;
                const float2 t0 = red[lr][0], t1 = red[lr][1];
                const float mean = (t0.x + t1.x) * (1.f / 128.f);
                const float var  = (t0.y + t1.y) * (1.f / 128.f) - mean * mean;
                const float inv  = rsqrtf(var + 1e-5f);
                float* cp = C + (size_t)(gr0 + 8 * h) * 128;
#pragma unroll
                for (int nt = 0; nt < 8; nt++) {
                    const int c0 = wn * 64 + nt * 8 + 2 * tig;
                    const float s0 = ln_s[c0], s1 = ln_s[c0 + 1];
                    const float b0 = ln_b[c0], b1 = ln_b[c0 + 1];
                    float2 ov;
                    ov.x = (acc[mt][nt][2 * h]     - mean) * inv * s0 + b0;
                    ov.y = (acc[mt][nt][2 * h + 1] - mean) * inv * s1 + b1;
                    *(float2*)(cp + c0) = ov;
                }
            }
        }
    } else {
#pragma unroll
        for (int mt = 0; mt < 2; mt++) {
            const int r0 = bm * 128 + wm * 32 + mt * 16 + gid;
#pragma unroll
            for (int nt = 0; nt < 8; nt++) {
                const int c0 = bn * 128 + wn * 64 + nt * 8 + 2 * tig;
                const float bi0 = bias[c0], bi1 = bias[c0 + 1];
                float v0 = acc[mt][nt][0] + bi0;
                float v1 = acc[mt][nt][1] + bi1;
                float v2 = acc[mt][nt][2] + bi0;
                float v3 = acc[mt][nt][3] + bi1;
                if (ACT == 1) { v0 = tanhf(v0); v1 = tanhf(v1); v2 = tanhf(v2); v3 = tanhf(v3); }
                else if (ACT == 2) { v0 = fmaxf(v0, 0.f); v1 = fmaxf(v1, 0.f); v2 = fmaxf(v2, 0.f); v3 = fmaxf(v3, 0.f); }
                *(float2*)(C + (size_t)r0 * N + c0)       = make_float2(v0, v1);
                *(float2*)(C + (size_t)(r0 + 8) * N + c0) = make_float2(v2, v3);
            }
        }
    }
}

// ---------------------------------------------------------------------------
// Scan. Per (b,j): m_{t+1} = a_t*m_t + c_t, a = mask?1:d, c = mask?0:(1-d)*w.
// pass1: per-chunk affine composition. pass2: warp Kogge-Stone across chunks.
// pass3: emit M[t].
// ---------------------------------------------------------------------------
__global__ void scan_pass1(const float* __restrict__ Wpre,
                           const unsigned char* __restrict__ mask,
                           const float* __restrict__ dlogit,
                           float* __restrict__ Aseg, float* __restrict__ Cseg)
{
    const int idx = blockIdx.x * blockDim.x + threadIdx.x;   // 0..2047
    const int ch  = blockIdx.y;
    const int b   = idx >> 7;
    const int j   = idx & 127;
    const float d  = 1.f / (1.f + expf(-dlogit[j]));
    const float om = 1.f - d;
    float A = 1.f, C = 0.f;
    const int t0 = ch * CHLEN;
#pragma unroll 4
    for (int t = t0; t < t0 + CHLEN; t++) {
        const bool mk = mask[t * BB + b] != 0;
        const float a = mk ? 1.f : d;
        const float c = mk ? 0.f : om * Wpre[(size_t)t * LANES + idx];
        A = a * A;
        C = a * C + c;
    }
    Aseg[ch * LANES + idx] = A;
    Cseg[ch * LANES + idx] = C;
}

__global__ void scan_pass2(const float* __restrict__ Aseg,
                           const float* __restrict__ Cseg,
                           const float* __restrict__ mem0,
                           float* __restrict__ Carry,
                           float* __restrict__ outFinal)
{
    const int idx  = blockIdx.x * 8 + (threadIdx.x >> 5);   // one warp per lane
    const int lane = threadIdx.x & 31;                       // = chunk
    float Av = Aseg[lane * LANES + idx];
    float Cv = Cseg[lane * LANES + idx];
#pragma unroll
    for (int off = 1; off < 32; off <<= 1) {
        const float pA = __shfl_up_sync(0xffffffffu, Av, off);
        const float pC = __shfl_up_sync(0xffffffffu, Cv, off);
        if (lane >= off) { Cv = Av * pC + Cv; Av = Av * pA; }
    }
    const float m0 = mem0[idx];
    const float incl = Av * m0 + Cv;                 // mem after chunk `lane`
    const float prev = __shfl_up_sync(0xffffffffu, incl, 1);
    const float enter = (lane == 0) ? m0 : prev;     // mem entering chunk
    Carry[lane * LANES + idx] = enter;
    if (lane == 31) outFinal[idx] = incl;
}

__global__ void scan_pass3(const float* __restrict__ Wpre,
                           const unsigned char* __restrict__ mask,
                           const float* __restrict__ dlogit,
                           const float* __restrict__ Carry,
                           float* __restrict__ Mbuf)
{
    const int idx = blockIdx.x * blockDim.x + threadIdx.x;
    const int ch  = blockIdx.y;
    const int b   = idx >> 7;
    const int j   = idx & 127;
    const float d  = 1.f / (1.f + expf(-dlogit[j]));
    const float om = 1.f - d;
    float m = Carry[ch * LANES + idx];
    const int t0 = ch * CHLEN;
#pragma unroll 4
    for (int t = t0; t < t0 + CHLEN; t++) {
        Mbuf[(size_t)t * LANES + idx] = m;
        const bool mk = mask[t * BB + b] != 0;
        const float w = Wpre[(size_t)t * LANES + idx];
        const float nm = d * m + om * w;
        m = mk ? m : nm;
    }
}

// ---------------------------------------------------------------------------
// Final: out = LN(X + UP) over D_MODEL=1024. One block (256 thr) per row.
// ---------------------------------------------------------------------------
__device__ __forceinline__ float blockReduceSum(float v, float* red)
{
    const int lane = threadIdx.x & 31, wid = threadIdx.x >> 5;
#pragma unroll
    for (int off = 16; off >= 1; off >>= 1) v += __shfl_xor_sync(0xffffffffu, v, off);
    if (lane == 0) red[wid] = v;
    __syncthreads();
    float t = (threadIdx.x < 8) ? red[threadIdx.x] : 0.f;
    if (wid == 0) {
#pragma unroll
        for (int off = 4; off >= 1; off >>= 1) t += __shfl_xor_sync(0xffffffffu, t, off);
        if (lane == 0) red[0] = t;
    }
    __syncthreads();
    const float r = red[0];
    __syncthreads();
    return r;
}

__global__ void __launch_bounds__(256)
ln_out_kernel(const float* __restrict__ X, const float* __restrict__ UP,
              const float* __restrict__ s, const float* __restrict__ b,
              float* __restrict__ O)
{
    __shared__ float red[8];
    const int row = blockIdx.x;
    const int tid = threadIdx.x;
    const float4 xv = *(const float4*)(X  + (size_t)row * DM + tid * 4);
    const float4 uv = *(const float4*)(UP + (size_t)row * DM + tid * 4);
    float v[4] = {xv.x + uv.x, xv.y + uv.y, xv.z + uv.z, xv.w + uv.w};
    float sum = v[0] + v[1] + v[2] + v[3];
    sum = blockReduceSum(sum, red);
    const float mean = sum * (1.f / DM);
    float vs = 0.f;
#pragma unroll
    for (int i = 0; i < 4; i++) { const float dd = v[i] - mean; vs += dd * dd; }
    vs = blockReduceSum(vs, red);
    const float inv = rsqrtf(vs * (1.f / DM) + 1e-5f);
    const float4 sv = *(const float4*)(s + tid * 4);
    const float4 bv = *(const float4*)(b + tid * 4);
    float4 ov;
    ov.x = (v[0] - mean) * inv * sv.x + bv.x;
    ov.y = (v[1] - mean) * inv * sv.y + bv.y;
    ov.z = (v[2] - mean) * inv * sv.z + bv.z;
    ov.w = (v[3] - mean) * inv * sv.w + bv.w;
    *(float4*)(O + (size_t)row * DM + tid * 4) = ov;
}

// ---------------------------------------------------------------------------
extern "C" void kernel_launch(void* const* d_in, const int* in_sizes, int n_in,
                              void* d_out, int out_size)
{
    const float*         x      = (const float*)d_in[0];
    const unsigned char* mask   = (const unsigned char*)d_in[1];
    const float*         mem0   = (const float*)d_in[2];
    const float*         Wb     = (const float*)d_in[3];
    const float*         b_bot  = (const float*)d_in[4];
    const float*         Wu     = (const float*)d_in[5];
    const float*         bu     = (const float*)d_in[6];
    const float*         Wr     = (const float*)d_in[7];
    const float*         br     = (const float*)d_in[8];
    const float*         Ww     = (const float*)d_in[9];
    const float*         bw     = (const float*)d_in[10];
    const float*         dlog   = (const float*)d_in[11];
    const float*         ff_w1  = (const float*)d_in[12];
    const float*         ff_b1  = (const float*)d_in[13];
    const float*         ff_w2  = (const float*)d_in[14];
    const float*         ff_b2  = (const float*)d_in[15];
    const float*         mln_s  = (const float*)d_in[16];
    const float*         mln_b  = (const float*)d_in[17];
    const float*         fln_s  = (const float*)d_in[18];
    const float*         fln_b  = (const float*)d_in[19];
    const float*         oln_s  = (const float*)d_in[20];
    const float*         oln_b  = (const float*)d_in[21];

    float* out = (float*)d_out;

    float *H, *Wpre, *M, *G, *U1, *G2, *UP, *Aseg, *Cseg, *Carry;
    cudaGetSymbolAddress((void**)&H,     g_H);
    cudaGetSymbolAddress((void**)&Wpre,  g_Wpre);
    cudaGetSymbolAddress((void**)&M,     g_M);
    cudaGetSymbolAddress((void**)&G,     g_G);
    cudaGetSymbolAddress((void**)&U1,    g_U1);
    cudaGetSymbolAddress((void**)&G2,    g_G2);
    cudaGetSymbolAddress((void**)&UP,    g_UP);
    cudaGetSymbolAddress((void**)&Aseg,  g_Aseg);
    cudaGetSymbolAddress((void**)&Cseg,  g_Cseg);
    cudaGetSymbolAddress((void**)&Carry, g_Carry);

    const int MR = RWS;  // 32768 rows

    // 1) H = X @ Wb + bb
    gemm_tf32<0,0><<<dim3(1, MR / 128), 256>>>(x, Wb, b_bot, nullptr, nullptr, nullptr,
                                               H, MR, DB, DM);
    // 2) Wpre = tanh(H @ Ww + bw)
    gemm_tf32<1,0><<<dim3(1, MR / 128), 256>>>(H, Ww, bw, nullptr, nullptr, nullptr,
                                               Wpre, MR, DB, DB);
    // 3) parallel diagonal scan -> M[t], final mem
    scan_pass1<<<dim3(8, NCH), 256>>>(Wpre, mask, dlog, Aseg, Cseg);
    scan_pass2<<<LANES / 8, 256>>>(Aseg, Cseg, mem0, Carry, out + OUT_MAIN);
    scan_pass3<<<dim3(8, NCH), 256>>>(Wpre, mask, dlog, Carry, M);
    // 4+5) G = LN(H + M@Wr + br)  [fused]
    gemm_tf32<0,1><<<dim3(1, MR / 128), 256>>>(M, Wr, br, H, mln_s, mln_b,
                                               G, MR, DB, DB);
    // 6) U1 = relu(G @ ff_w1 + ff_b1)
    gemm_tf32<2,0><<<dim3(DH / 128, MR / 128), 256>>>(G, ff_w1, ff_b1, nullptr, nullptr, nullptr,
                                                      U1, MR, DH, DB);
    // 7+8) G2 = LN(G + U1@ff_w2 + ff_b2)  [fused]
    gemm_tf32<0,1><<<dim3(1, MR / 128), 256>>>(U1, ff_w2, ff_b2, G, fln_s, fln_b,
                                               G2, MR, DB, DH);
    // 9) UP = G2 @ Wu + bu
    gemm_tf32<0,0><<<dim3(DM / 128, MR / 128), 256>>>(G2, Wu, bu, nullptr, nullptr, nullptr,
                                                      UP, MR, DM, DB);
    // 10) out = LN(X + UP)
    ln_out_kernel<<<MR, 256>>>(x, UP, oln_s, oln_b, out);
}

// round 5
// speedup vs baseline: 2.4873x; 1.1491x over previous
#include <cuda_runtime.h>
#include <cstdint>

// Problem dims
#define TT 2048
#define BB 16
#define DM 1024
#define DB 128
#define DH 512
#define RWS (TT*BB)                 // 32768 rows
#define OUT_MAIN ((size_t)RWS*DM)   // offset of final_mem in d_out

#define NCH 32                      // scan chunks
#define CHLEN (TT/NCH)              // 64
#define LANES (BB*DB)               // 2048 scan lanes

// Scratch (device globals; no runtime allocation allowed)
__device__ float g_H   [RWS*DB];
__device__ float g_Wpre[RWS*DB];
__device__ float g_M   [RWS*DB];
__device__ float g_G   [RWS*DB];
__device__ float g_U1  [RWS*DH];
__device__ float g_G2  [RWS*DB];
__device__ float g_UP  [RWS*DM];
__device__ float g_Aseg [NCH*LANES];
__device__ float g_Cseg [NCH*LANES];
__device__ float g_Carry[NCH*LANES];
// transformed weights: [N][K], k-permuted+swizzled, tf32-truncated
__device__ float g_WbT [DB*DM];
__device__ float g_WwT [DB*DB];
__device__ float g_WrT [DB*DB];
__device__ float g_W1T [DH*DB];
__device__ float g_W2T [DB*DH];
__device__ float g_WuT [DM*DB];

// ---------------------------------------------------------------------------
__device__ __forceinline__ float to_tf32(float x) {
    uint32_t u;
    asm("cvt.rna.tf32.f32 %0, %1;" : "=r"(u) : "f"(x));
    return __uint_as_float(u);
}

__device__ __forceinline__ void mma_tf32(float* d, const float* a, const float* b) {
    asm volatile(
        "mma.sync.aligned.m16n8k8.row.col.f32.tf32.tf32.f32 "
        "{%0,%1,%2,%3}, {%4,%5,%6,%7}, {%8,%9}, {%0,%1,%2,%3};"
        : "+f"(d[0]), "+f"(d[1]), "+f"(d[2]), "+f"(d[3])
        : "r"(__float_as_uint(a[0])), "r"(__float_as_uint(a[1])),
          "r"(__float_as_uint(a[2])), "r"(__float_as_uint(a[3])),
          "r"(__float_as_uint(b[0])), "r"(__float_as_uint(b[1])));
}

__device__ __forceinline__ void cp_async16(void* smem_dst, const void* gmem_src) {
    unsigned dst = (unsigned)__cvta_generic_to_shared(smem_dst);
    asm volatile("cp.async.ca.shared.global [%0], [%1], 16;" :: "r"(dst), "l"(gmem_src));
}
__device__ __forceinline__ void cp_async_commit() {
    asm volatile("cp.async.commit_group;");
}
__device__ __forceinline__ void cp_async_wait_all() {
    asm volatile("cp.async.wait_group 0;" ::: "memory");
}

// ---------------------------------------------------------------------------
// Weight prep: Wt[n][pos(k)] = tf32(W[k][n]), pos within 16-k groups:
//   kk=k&15: pos = g*16 + ((kk&3) ^ ((n>>1)&3))*4 + (kk>>2)
// Matches the GEMM's smem layout so cp.async copies verbatim and fragment
// lds.128 at (tig ^ ((n>>1)&3))*4 yields k = {tig, tig+4, tig+8, tig+12}.
// ---------------------------------------------------------------------------
__global__ void prep_weights(const float* __restrict__ Wb, const float* __restrict__ Ww,
                             const float* __restrict__ Wr, const float* __restrict__ W1,
                             const float* __restrict__ W2, const float* __restrict__ Wu,
                             float* __restrict__ WbT, float* __restrict__ WwT,
                             float* __restrict__ WrT, float* __restrict__ W1T,
                             float* __restrict__ W2T, float* __restrict__ WuT)
{
    const int wsel = blockIdx.y;
    const float* W; float* Wt; int K, N;
    switch (wsel) {
        case 0: W = Wb; Wt = WbT; K = DM; N = DB; break;
        case 1: W = Ww; Wt = WwT; K = DB; N = DB; break;
        case 2: W = Wr; Wt = WrT; K = DB; N = DB; break;
        case 3: W = W1; Wt = W1T; K = DB; N = DH; break;
        case 4: W = W2; Wt = W2T; K = DH; N = DB; break;
        default: W = Wu; Wt = WuT; K = DB; N = DM; break;
    }
    const int idx = blockIdx.x * blockDim.x + threadIdx.x;
    if (idx >= K * N) return;
    const int k = idx / N, n = idx % N;
    const int kk = k & 15, g = k >> 4;
    const int pos = g * 16 + (((kk & 3) ^ ((n >> 1) & 3)) << 2) + (kk >> 2);
    Wt[(size_t)n * K + pos] = to_tf32(W[idx]);
}

// ---------------------------------------------------------------------------
// TF32 GEMM: C = act(A[M,K] @ W[K,N] + bias)  (+optional fused residual+LN)
// BM=128, BN=128, BK=16, 256 threads, 8 warps (4m x 2n), warp tile 32x64.
// A: register-staged from plain gmem into k-perm + XOR-swizzled smem.
// B: cp.async from pre-transformed weights (already in that layout).
// ACT: 0 none, 1 tanh, 2 relu.  FUSE_LN: epilogue does LN(acc+bias+resid).
// ---------------------------------------------------------------------------
template<int ACT, int FUSE_LN>
__global__ void __launch_bounds__(256)
gemm_tf32(const float* __restrict__ A, const float* __restrict__ Wt,
          const float* __restrict__ bias,
          const float* __restrict__ resid,
          const float* __restrict__ ln_s, const float* __restrict__ ln_b,
          float* __restrict__ C, int M, int N, int K)
{
    __shared__ __align__(16) float As[2][128 * 16];
    __shared__ __align__(16) float Bs[2][128 * 16];
    __shared__ float2 red[128][2];

    const int tid  = threadIdx.x;
    const int warp = tid >> 5, lane = tid & 31;
    const int gid  = lane >> 2, tig = lane & 3;
    const int wm   = warp >> 1, wn = warp & 1;
    const int bm   = blockIdx.y, bn = blockIdx.x;

    const float* Ablk = A + (size_t)bm * 128 * K;

    // A loader: thread -> (row, 8 k-elements)
    const int aRow = tid >> 1;            // 0..127
    const int aQ   = (tid & 1) * 2;       // gmem chunk pair: {0,1} or {2,3}
    const int aSw  = (aRow >> 1) & 3;     // XOR swizzle for this row
    // B loader (cp.async): thread -> (n-row, 2 chunks)
    const int bN   = tid >> 1;            // 0..127
    const int bC   = (tid & 1) * 2;       // chunks {0,1} or {2,3}
    const float* Bsrc = Wt + (size_t)(bn * 128 + bN) * K + bC * 4;

    float acc[2][8][4];
#pragma unroll
    for (int mt = 0; mt < 2; mt++)
#pragma unroll
        for (int nt = 0; nt < 8; nt++)
#pragma unroll
            for (int i = 0; i < 4; i++) acc[mt][nt][i] = 0.f;

    // helper lambda-ish macros for A store
#define A_STORE(dst, v0, v1)                                                 \
    {                                                                        \
        float* as_ = (dst) + aRow * 16;                                      \
        as_[((0 ^ aSw) << 2) + aQ]     = to_tf32((v0).x);                    \
        as_[((1 ^ aSw) << 2) + aQ]     = to_tf32((v0).y);                    \
        as_[((2 ^ aSw) << 2) + aQ]     = to_tf32((v0).z);                    \
        as_[((3 ^ aSw) << 2) + aQ]     = to_tf32((v0).w);                    \
        as_[((0 ^ aSw) << 2) + aQ + 1] = to_tf32((v1).x);                    \
        as_[((1 ^ aSw) << 2) + aQ + 1] = to_tf32((v1).y);                    \
        as_[((2 ^ aSw) << 2) + aQ + 1] = to_tf32((v1).z);                    \
        as_[((3 ^ aSw) << 2) + aQ + 1] = to_tf32((v1).w);                    \
    }

    // --- stage tile 0 ---
    {
        cp_async16(&Bs[0][bN * 16 + bC * 4],     Bsrc);
        cp_async16(&Bs[0][bN * 16 + bC * 4 + 4], Bsrc + 4);
        cp_async_commit();
        float4 va0 = *(const float4*)(Ablk + (size_t)aRow * K + aQ * 4);
        float4 va1 = *(const float4*)(Ablk + (size_t)aRow * K + aQ * 4 + 4);
        A_STORE(As[0], va0, va1);
        cp_async_wait_all();
    }
    __syncthreads();

    const int nt_tiles = K >> 4;
    int buf = 0;
    for (int t = 0; t < nt_tiles; t++) {
        const bool has_next = (t + 1) < nt_tiles;
        float4 na0, na1;
        if (has_next) {
            const int k0n = (t + 1) << 4;
            cp_async16(&Bs[buf ^ 1][bN * 16 + bC * 4],     Bsrc + k0n);
            cp_async16(&Bs[buf ^ 1][bN * 16 + bC * 4 + 4], Bsrc + k0n + 4);
            cp_async_commit();
            na0 = *(const float4*)(Ablk + (size_t)aRow * K + k0n + aQ * 4);
            na1 = *(const float4*)(Ablk + (size_t)aRow * K + k0n + aQ * 4 + 4);
        }

        const float* as_ = As[buf];
        const float* bs_ = Bs[buf];

        // A fragments: one lds.128 per (mt, row-half) -> k = tig,tig+4,tig+8,tig+12
        float4 a0[2], a1[2];
#pragma unroll
        for (int mt = 0; mt < 2; mt++) {
            const int r0 = wm * 32 + mt * 16 + gid;
            const int r1 = r0 + 8;
            a0[mt] = *(const float4*)&as_[r0 * 16 + ((tig ^ ((r0 >> 1) & 3)) << 2)];
            a1[mt] = *(const float4*)&as_[r1 * 16 + ((tig ^ ((r1 >> 1) & 3)) << 2)];
        }

#pragma unroll
        for (int nh = 0; nh < 2; nh++) {
            float4 b4[4];
#pragma unroll
            for (int q = 0; q < 4; q++) {
                const int n = wn * 64 + (nh * 4 + q) * 8 + gid;
                b4[q] = *(const float4*)&bs_[n * 16 + ((tig ^ ((n >> 1) & 3)) << 2)];
            }
#pragma unroll
            for (int ph = 0; ph < 2; ph++) {
#pragma unroll
                for (int mt = 0; mt < 2; mt++) {
                    float af[4];
                    if (ph == 0) {
                        af[0] = a0[mt].x; af[1] = a1[mt].x;
                        af[2] = a0[mt].y; af[3] = a1[mt].y;
                    } else {
                        af[0] = a0[mt].z; af[1] = a1[mt].z;
                        af[2] = a0[mt].w; af[3] = a1[mt].w;
                    }
#pragma unroll
                    for (int q = 0; q < 4; q++) {
                        float bf[2];
                        bf[0] = (ph == 0) ? b4[q].x : b4[q].z;
                        bf[1] = (ph == 0) ? b4[q].y : b4[q].w;
                        mma_tf32(acc[mt][nh * 4 + q], af, bf);
                    }
                }
            }
        }

        if (has_next) {
            A_STORE(As[buf ^ 1], na0, na1);
            cp_async_wait_all();
            __syncthreads();
            buf ^= 1;
        }
    }
#undef A_STORE

    // ---------------- Epilogue ----------------
    if (FUSE_LN) {
        float sum[2][2], sq[2][2];
#pragma unroll
        for (int mt = 0; mt < 2; mt++) { sum[mt][0] = sum[mt][1] = 0.f; sq[mt][0] = sq[mt][1] = 0.f; }

#pragma unroll
        for (int mt = 0; mt < 2; mt++) {
            const int gr0 = bm * 128 + wm * 32 + mt * 16 + gid;
#pragma unroll
            for (int nt = 0; nt < 8; nt++) {
                const int c0 = wn * 64 + nt * 8 + 2 * tig;
                const float bi0 = bias[c0], bi1 = bias[c0 + 1];
                const float2 rA = *(const float2*)(resid + (size_t)gr0 * 128 + c0);
                const float2 rB = *(const float2*)(resid + (size_t)(gr0 + 8) * 128 + c0);
                acc[mt][nt][0] += bi0 + rA.x;
                acc[mt][nt][1] += bi1 + rA.y;
                acc[mt][nt][2] += bi0 + rB.x;
                acc[mt][nt][3] += bi1 + rB.y;
#pragma unroll
                for (int h = 0; h < 2; h++) {
                    const float v0 = acc[mt][nt][2 * h], v1 = acc[mt][nt][2 * h + 1];
                    sum[mt][h] += v0 + v1;
                    sq[mt][h]  += v0 * v0 + v1 * v1;
                }
            }
        }
#pragma unroll
        for (int mt = 0; mt < 2; mt++)
#pragma unroll
            for (int h = 0; h < 2; h++) {
#pragma unroll
                for (int off = 1; off <= 2; off <<= 1) {
                    sum[mt][h] += __shfl_xor_sync(0xffffffffu, sum[mt][h], off);
                    sq[mt][h]  += __shfl_xor_sync(0xffffffffu, sq[mt][h], off);
                }
            }
        if (tig == 0) {
#pragma unroll
            for (int mt = 0; mt < 2; mt++) {
                const int lr0 = wm * 32 + mt * 16 + gid;
                red[lr0][wn]     = make_float2(sum[mt][0], sq[mt][0]);
                red[lr0 + 8][wn] = make_float2(sum[mt][1], sq[mt][1]);
            }
        }
        __syncthreads();

#pragma unroll
        for (int mt = 0; mt < 2; mt++) {
            const int lr0 = wm * 32 + mt * 16 + gid;
            const int gr0 = bm * 128 + lr0;
#pragma unroll
            for (int h = 0; h < 2; h++) {
                const int lr = lr0 + 8 * h;
                const float2 t0 = red[lr][0], t1 = red[lr][1];
                const float mean = (t0.x + t1.x) * (1.f / 128.f);
                const float var  = (t0.y + t1.y) * (1.f / 128.f) - mean * mean;
                const float inv  = rsqrtf(var + 1e-5f);
                float* cp = C + (size_t)(gr0 + 8 * h) * 128;
#pragma unroll
                for (int nt = 0; nt < 8; nt++) {
                    const int c0 = wn * 64 + nt * 8 + 2 * tig;
                    const float s0 = ln_s[c0], s1 = ln_s[c0 + 1];
                    const float b0 = ln_b[c0], b1 = ln_b[c0 + 1];
                    float2 ov;
                    ov.x = (acc[mt][nt][2 * h]     - mean) * inv * s0 + b0;
                    ov.y = (acc[mt][nt][2 * h + 1] - mean) * inv * s1 + b1;
                    *(float2*)(cp + c0) = ov;
                }
            }
        }
    } else {
#pragma unroll
        for (int mt = 0; mt < 2; mt++) {
            const int r0 = bm * 128 + wm * 32 + mt * 16 + gid;
#pragma unroll
            for (int nt = 0; nt < 8; nt++) {
                const int c0 = bn * 128 + wn * 64 + nt * 8 + 2 * tig;
                const float bi0 = bias[c0], bi1 = bias[c0 + 1];
                float v0 = acc[mt][nt][0] + bi0;
                float v1 = acc[mt][nt][1] + bi1;
                float v2 = acc[mt][nt][2] + bi0;
                float v3 = acc[mt][nt][3] + bi1;
                if (ACT == 1) { v0 = tanhf(v0); v1 = tanhf(v1); v2 = tanhf(v2); v3 = tanhf(v3); }
                else if (ACT == 2) { v0 = fmaxf(v0, 0.f); v1 = fmaxf(v1, 0.f); v2 = fmaxf(v2, 0.f); v3 = fmaxf(v3, 0.f); }
                *(float2*)(C + (size_t)r0 * N + c0)       = make_float2(v0, v1);
                *(float2*)(C + (size_t)(r0 + 8) * N + c0) = make_float2(v2, v3);
            }
        }
    }
}

// ---------------------------------------------------------------------------
// Scan (3-pass, warp Kogge-Stone in pass2)
// ---------------------------------------------------------------------------
__global__ void scan_pass1(const float* __restrict__ Wpre,
                           const unsigned char* __restrict__ mask,
                           const float* __restrict__ dlogit,
                           float* __restrict__ Aseg, float* __restrict__ Cseg)
{
    const int idx = blockIdx.x * blockDim.x + threadIdx.x;
    const int ch  = blockIdx.y;
    const int b   = idx >> 7;
    const int j   = idx & 127;
    const float d  = 1.f / (1.f + expf(-dlogit[j]));
    const float om = 1.f - d;
    float A = 1.f, C = 0.f;
    const int t0 = ch * CHLEN;
#pragma unroll 4
    for (int t = t0; t < t0 + CHLEN; t++) {
        const bool mk = mask[t * BB + b] != 0;
        const float a = mk ? 1.f : d;
        const float c = mk ? 0.f : om * Wpre[(size_t)t * LANES + idx];
        A = a * A;
        C = a * C + c;
    }
    Aseg[ch * LANES + idx] = A;
    Cseg[ch * LANES + idx] = C;
}

__global__ void scan_pass2(const float* __restrict__ Aseg,
                           const float* __restrict__ Cseg,
                           const float* __restrict__ mem0,
                           float* __restrict__ Carry,
                           float* __restrict__ outFinal)
{
    const int idx  = blockIdx.x * 8 + (threadIdx.x >> 5);
    const int lane = threadIdx.x & 31;
    float Av = Aseg[lane * LANES + idx];
    float Cv = Cseg[lane * LANES + idx];
#pragma unroll
    for (int off = 1; off < 32; off <<= 1) {
        const float pA = __shfl_up_sync(0xffffffffu, Av, off);
        const float pC = __shfl_up_sync(0xffffffffu, Cv, off);
        if (lane >= off) { Cv = Av * pC + Cv; Av = Av * pA; }
    }
    const float m0 = mem0[idx];
    const float incl = Av * m0 + Cv;
    const float prev = __shfl_up_sync(0xffffffffu, incl, 1);
    const float enter = (lane == 0) ? m0 : prev;
    Carry[lane * LANES + idx] = enter;
    if (lane == 31) outFinal[idx] = incl;
}

__global__ void scan_pass3(const float* __restrict__ Wpre,
                           const unsigned char* __restrict__ mask,
                           const float* __restrict__ dlogit,
                           const float* __restrict__ Carry,
                           float* __restrict__ Mbuf)
{
    const int idx = blockIdx.x * blockDim.x + threadIdx.x;
    const int ch  = blockIdx.y;
    const int b   = idx >> 7;
    const int j   = idx & 127;
    const float d  = 1.f / (1.f + expf(-dlogit[j]));
    const float om = 1.f - d;
    float m = Carry[ch * LANES + idx];
    const int t0 = ch * CHLEN;
#pragma unroll 4
    for (int t = t0; t < t0 + CHLEN; t++) {
        Mbuf[(size_t)t * LANES + idx] = m;
        const bool mk = mask[t * BB + b] != 0;
        const float w = Wpre[(size_t)t * LANES + idx];
        const float nm = d * m + om * w;
        m = mk ? m : nm;
    }
}

// ---------------------------------------------------------------------------
// Final: out = LN(X + UP) over D_MODEL=1024, single-pass stats.
// ---------------------------------------------------------------------------
__global__ void __launch_bounds__(256)
ln_out_kernel(const float* __restrict__ X, const float* __restrict__ UP,
              const float* __restrict__ s, const float* __restrict__ b,
              float* __restrict__ O)
{
    __shared__ float2 red[8];
    const int row = blockIdx.x;
    const int tid = threadIdx.x;
    const int lane = tid & 31, wid = tid >> 5;
    const float4 xv = *(const float4*)(X  + (size_t)row * DM + tid * 4);
    const float4 uv = *(const float4*)(UP + (size_t)row * DM + tid * 4);
    float v[4] = {xv.x + uv.x, xv.y + uv.y, xv.z + uv.z, xv.w + uv.w};
    float2 st = make_float2(0.f, 0.f);
#pragma unroll
    for (int i = 0; i < 4; i++) { st.x += v[i]; st.y += v[i] * v[i]; }
#pragma unroll
    for (int off = 16; off >= 1; off >>= 1) {
        st.x += __shfl_xor_sync(0xffffffffu, st.x, off);
        st.y += __shfl_xor_sync(0xffffffffu, st.y, off);
    }
    if (lane == 0) red[wid] = st;
    __syncthreads();
    float2 t = (lane < 8) ? red[lane] : make_float2(0.f, 0.f);
#pragma unroll
    for (int off = 4; off >= 1; off >>= 1) {
        t.x += __shfl_xor_sync(0xffffffffu, t.x, off);
        t.y += __shfl_xor_sync(0xffffffffu, t.y, off);
    }
    t.x = __shfl_sync(0xffffffffu, t.x, 0);
    t.y = __shfl_sync(0xffffffffu, t.y, 0);
    const float mean = t.x * (1.f / DM);
    const float var  = t.y * (1.f / DM) - mean * mean;
    const float inv  = rsqrtf(var + 1e-5f);
    const float4 sv = *(const float4*)(s + tid * 4);
    const float4 bv = *(const float4*)(b + tid * 4);
    float4 ov;
    ov.x = (v[0] - mean) * inv * sv.x + bv.x;
    ov.y = (v[1] - mean) * inv * sv.y + bv.y;
    ov.z = (v[2] - mean) * inv * sv.z + bv.z;
    ov.w = (v[3] - mean) * inv * sv.w + bv.w;
    *(float4*)(O + (size_t)row * DM + tid * 4) = ov;
}

// ---------------------------------------------------------------------------
extern "C" void kernel_launch(void* const* d_in, const int* in_sizes, int n_in,
                              void* d_out, int out_size)
{
    const float*         x      = (const float*)d_in[0];
    const unsigned char* mask   = (const unsigned char*)d_in[1];
    const float*         mem0   = (const float*)d_in[2];
    const float*         Wb     = (const float*)d_in[3];
    const float*         b_bot  = (const float*)d_in[4];
    const float*         Wu     = (const float*)d_in[5];
    const float*         bu     = (const float*)d_in[6];
    const float*         Wr     = (const float*)d_in[7];
    const float*         br     = (const float*)d_in[8];
    const float*         Ww     = (const float*)d_in[9];
    const float*         bw     = (const float*)d_in[10];
    const float*         dlog   = (const float*)d_in[11];
    const float*         ff_w1  = (const float*)d_in[12];
    const float*         ff_b1  = (const float*)d_in[13];
    const float*         ff_w2  = (const float*)d_in[14];
    const float*         ff_b2  = (const float*)d_in[15];
    const float*         mln_s  = (const float*)d_in[16];
    const float*         mln_b  = (const float*)d_in[17];
    const float*         fln_s  = (const float*)d_in[18];
    const float*         fln_b  = (const float*)d_in[19];
    const float*         oln_s  = (const float*)d_in[20];
    const float*         oln_b  = (const float*)d_in[21];

    float* out = (float*)d_out;

    float *H, *Wpre, *M, *G, *U1, *G2, *UP, *Aseg, *Cseg, *Carry;
    float *WbT, *WwT, *WrT, *W1T, *W2T, *WuT;
    cudaGetSymbolAddress((void**)&H,     g_H);
    cudaGetSymbolAddress((void**)&Wpre,  g_Wpre);
    cudaGetSymbolAddress((void**)&M,     g_M);
    cudaGetSymbolAddress((void**)&G,     g_G);
    cudaGetSymbolAddress((void**)&U1,    g_U1);
    cudaGetSymbolAddress((void**)&G2,    g_G2);
    cudaGetSymbolAddress((void**)&UP,    g_UP);
    cudaGetSymbolAddress((void**)&Aseg,  g_Aseg);
    cudaGetSymbolAddress((void**)&Cseg,  g_Cseg);
    cudaGetSymbolAddress((void**)&Carry, g_Carry);
    cudaGetSymbolAddress((void**)&WbT,   g_WbT);
    cudaGetSymbolAddress((void**)&WwT,   g_WwT);
    cudaGetSymbolAddress((void**)&WrT,   g_WrT);
    cudaGetSymbolAddress((void**)&W1T,   g_W1T);
    cudaGetSymbolAddress((void**)&W2T,   g_W2T);
    cudaGetSymbolAddress((void**)&WuT,   g_WuT);

    const int MR = RWS;  // 32768 rows

    // 0) transform weights (transpose + k-perm + swizzle + tf32)
    prep_weights<<<dim3(512, 6), 256>>>(Wb, Ww, Wr, ff_w1, ff_w2, Wu,
                                        WbT, WwT, WrT, W1T, W2T, WuT);
    // 1) H = X @ Wb + bb
    gemm_tf32<0,0><<<dim3(1, MR / 128), 256>>>(x, WbT, b_bot, nullptr, nullptr, nullptr,
                                               H, MR, DB, DM);
    // 2) Wpre = tanh(H @ Ww + bw)
    gemm_tf32<1,0><<<dim3(1, MR / 128), 256>>>(H, WwT, bw, nullptr, nullptr, nullptr,
                                               Wpre, MR, DB, DB);
    // 3) parallel diagonal scan -> M[t], final mem
    scan_pass1<<<dim3(8, NCH), 256>>>(Wpre, mask, dlog, Aseg, Cseg);
    scan_pass2<<<LANES / 8, 256>>>(Aseg, Cseg, mem0, Carry, out + OUT_MAIN);
    scan_pass3<<<dim3(8, NCH), 256>>>(Wpre, mask, dlog, Carry, M);
    // 4+5) G = LN(H + M@Wr + br)  [fused]
    gemm_tf32<0,1><<<dim3(1, MR / 128), 256>>>(M, WrT, br, H, mln_s, mln_b,
                                               G, MR, DB, DB);
    // 6) U1 = relu(G @ ff_w1 + ff_b1)
    gemm_tf32<2,0><<<dim3(DH / 128, MR / 128), 256>>>(G, W1T, ff_b1, nullptr, nullptr, nullptr,
                                                      U1, MR, DH, DB);
    // 7+8) G2 = LN(G + U1@ff_w2 + ff_b2)  [fused]
    gemm_tf32<0,1><<<dim3(1, MR / 128), 256>>>(U1, W2T, ff_b2, G, fln_s, fln_b,
                                               G2, MR, DB, DH);
    // 9) UP = G2 @ Wu + bu
    gemm_tf32<0,0><<<dim3(DM / 128, MR / 128), 256>>>(G2, WuT, bu, nullptr, nullptr, nullptr,
                                                      UP, MR, DM, DB);
    // 10) out = LN(X + UP)
    ln_out_kernel<<<MR, 256>>>(x, UP, oln_s, oln_b, out);
}